// round 5
// baseline (speedup 1.0000x reference)
#include <cuda_runtime.h>
#include <cstdint>

#define FULLMASK 0xffffffffu

constexpr int Bv   = 2;
constexpr int Tv   = 2048;
constexpr int EMB  = 2048;
constexpr int Hh   = 16;
constexpr int HD   = 128;
constexpr int Mrows = Bv * Tv;   // 4096

// Scratch (no allocation allowed -> device globals)
__device__ float g_q[Mrows * EMB];
__device__ float g_k[Mrows * EMB];
__device__ float g_v[Mrows * EMB];
__device__ float g_o[Mrows * EMB];

// ---------------- helpers ----------------

__device__ __forceinline__ uint32_t f2tf(float x) {
    uint32_t r;
    asm("cvt.rna.tf32.f32 %0, %1;" : "=r"(r) : "f"(x));
    return r;
}
__device__ __forceinline__ float f2tff(float x) { return __uint_as_float(f2tf(x)); }

__device__ __forceinline__ void mma_tf32(float c[4], const uint32_t a[4],
                                         uint32_t b0, uint32_t b1) {
    asm volatile(
        "mma.sync.aligned.m16n8k8.row.col.f32.tf32.tf32.f32 "
        "{%0,%1,%2,%3},{%4,%5,%6,%7},{%8,%9},{%0,%1,%2,%3};"
        : "+f"(c[0]), "+f"(c[1]), "+f"(c[2]), "+f"(c[3])
        : "r"(a[0]), "r"(a[1]), "r"(a[2]), "r"(a[3]), "r"(b0), "r"(b1));
}

__device__ __forceinline__ void cpasync16(uint32_t dst, const void* src) {
    asm volatile("cp.async.cg.shared.global [%0], [%1], 16;" ::"r"(dst), "l"(src));
}

// ---------------- GEMM: C[m][n] = sum_k A[m][k] * W[n][k] ----------------
// BM=128, BN=128, BK=32, 256 threads, tf32 mma, cp.async 2-stage.
// blockIdx.z selects (W, C) pair for the fused QKV launch.

constexpr int G_STAGE = 128 * 36;  // floats per tile stage (pad 32->36)

__global__ __launch_bounds__(256) void gemm_nt(
    const float* __restrict__ A,
    const float* __restrict__ W0, const float* __restrict__ W1, const float* __restrict__ W2,
    float* __restrict__ C0, float* __restrict__ C1, float* __restrict__ C2,
    int M, int N, int K) {
    const float* W = (blockIdx.z == 0) ? W0 : (blockIdx.z == 1 ? W1 : W2);
    float* C = (blockIdx.z == 0) ? C0 : (blockIdx.z == 1 ? C1 : C2);

    extern __shared__ float sm[];
    float* As = sm;                 // 2 stages
    float* Bs = sm + 2 * G_STAGE;   // 2 stages

    const int tid = threadIdx.x;
    const int bm = blockIdx.y * 128;
    const int bn = blockIdx.x * 128;
    const float* Ag = A + (size_t)bm * K;
    const float* Wg = W + (size_t)bn * K;

    const uint32_t asBase = (uint32_t)__cvta_generic_to_shared(As);
    const uint32_t bsBase = (uint32_t)__cvta_generic_to_shared(Bs);

    const int wid = tid >> 5, lane = tid & 31;
    const int g = lane >> 2, m4 = lane & 3;
    const int wm = wid >> 1, wn = wid & 1;

    float acc[2][8][4];
#pragma unroll
    for (int mi = 0; mi < 2; mi++)
#pragma unroll
        for (int ni = 0; ni < 8; ni++)
#pragma unroll
            for (int q = 0; q < 4; q++) acc[mi][ni][q] = 0.f;

    auto load_stage = [&](int st, int kt) {
        uint32_t aoff = asBase + (uint32_t)st * G_STAGE * 4;
        uint32_t boff = bsBase + (uint32_t)st * G_STAGE * 4;
#pragma unroll
        for (int p = 0; p < 4; p++) {
            int id = tid + 256 * p;
            int r = id >> 3;
            int c = (id & 7) << 2;
            cpasync16(aoff + (uint32_t)(r * 36 + c) * 4, Ag + (size_t)r * K + kt + c);
            cpasync16(boff + (uint32_t)(r * 36 + c) * 4, Wg + (size_t)r * K + kt + c);
        }
        asm volatile("cp.async.commit_group;");
    };

    const int NIT = K / 32;
    load_stage(0, 0);

    for (int it = 0; it < NIT; ++it) {
        if (it + 1 < NIT) {
            load_stage((it + 1) & 1, (it + 1) * 32);
            asm volatile("cp.async.wait_group 1;");
        } else {
            asm volatile("cp.async.wait_group 0;");
        }
        __syncthreads();

        const float* as = As + (it & 1) * G_STAGE;
        const float* bs = Bs + (it & 1) * G_STAGE;

#pragma unroll
        for (int kk = 0; kk < 32; kk += 8) {
            uint32_t a[2][4], b[8][2];
#pragma unroll
            for (int mi = 0; mi < 2; mi++) {
                const float* ap = as + (wm * 32 + mi * 16 + g) * 36 + kk + m4;
                a[mi][0] = f2tf(ap[0]);
                a[mi][1] = f2tf(ap[8 * 36]);
                a[mi][2] = f2tf(ap[4]);
                a[mi][3] = f2tf(ap[8 * 36 + 4]);
            }
#pragma unroll
            for (int ni = 0; ni < 8; ni++) {
                const float* bp = bs + (wn * 64 + ni * 8 + g) * 36 + kk + m4;
                b[ni][0] = f2tf(bp[0]);
                b[ni][1] = f2tf(bp[4]);
            }
#pragma unroll
            for (int mi = 0; mi < 2; mi++)
#pragma unroll
                for (int ni = 0; ni < 8; ni++)
                    mma_tf32(acc[mi][ni], a[mi], b[ni][0], b[ni][1]);
        }
        __syncthreads();
    }

#pragma unroll
    for (int mi = 0; mi < 2; mi++) {
        int r0 = bm + wm * 32 + mi * 16 + g;
#pragma unroll
        for (int ni = 0; ni < 8; ni++) {
            int col = bn + wn * 64 + ni * 8 + 2 * m4;
            float2 v0 = make_float2(acc[mi][ni][0], acc[mi][ni][1]);
            float2 v1 = make_float2(acc[mi][ni][2], acc[mi][ni][3]);
            *(float2*)&C[(size_t)r0 * N + col] = v0;
            *(float2*)&C[(size_t)(r0 + 8) * N + col] = v1;
        }
    }
}

// ---------------- RoPE (interleaved pairs) on Q and K ----------------

__global__ void rope_kernel(float* __restrict__ q, float* __restrict__ k,
                            const float* __restrict__ cosv, const float* __restrict__ sinv) {
    int i = blockIdx.x * blockDim.x + threadIdx.x;  // Mrows*Hh*64 threads
    int d2 = i & 63;
    int h = (i >> 6) & 15;
    int row = i >> 10;            // b*T + t
    int t = row & (Tv - 1);
    float c = cosv[t * 64 + d2];
    float s = sinv[t * 64 + d2];
    size_t base = (size_t)row * EMB + h * HD + 2 * d2;
    float2 qv = *(float2*)(q + base);
    float2 kv = *(float2*)(k + base);
    float2 qo = make_float2(qv.x * c - qv.y * s, qv.x * s + qv.y * c);
    float2 ko = make_float2(kv.x * c - kv.y * s, kv.x * s + kv.y * c);
    *(float2*)(q + base) = qo;
    *(float2*)(k + base) = ko;
}

// ---------------- Flash attention (non-causal), tf32 mma ----------------
// Br=128 (8 warps x 16 rows), Bc=64, HD=128.
// smem: region0 = Q staging [128][132] (reused as K[64][132] + V[64][132]),
//       Ps [128][68] for the P smem roundtrip (per-warp rows -> __syncwarp only).

constexpr int ATT_SMEM_FLOATS = 128 * 132 + 128 * 68;  // 25600 -> 102400 B

__global__ __launch_bounds__(256, 1) void attn_kernel(
    const float* __restrict__ Q, const float* __restrict__ Kg,
    const float* __restrict__ Vg, float* __restrict__ O) {
    extern __shared__ float sm[];
    float* Ks = sm;
    float* Vs = sm + 64 * 132;
    float* Ps = sm + 128 * 132;

    const int tid = threadIdx.x, wid = tid >> 5, lane = tid & 31;
    const int g = lane >> 2, m4 = lane & 3;
    const int qb = blockIdx.x;
    const int b = blockIdx.y >> 4, h = blockIdx.y & 15;

    // fold 1/sqrt(HD) * log2(e) into Q so softmax is pure exp2
    const float kScale = 0.08838834764831845f * 1.4426950408889634f;

    const size_t headoff = (size_t)h * HD;
    const float* Qg = Q + ((size_t)(b * Tv) + (size_t)qb * 128) * EMB + headoff;

    // stage Q tile (scaled + tf32-rounded) into smem
#pragma unroll
    for (int p = 0; p < 16; p++) {
        int id = tid + 256 * p;
        int r = id >> 5;
        int c = (id & 31) << 2;
        float4 v = *(const float4*)(Qg + (size_t)r * EMB + c);
        float* dst = sm + r * 132 + c;
        dst[0] = f2tff(v.x * kScale);
        dst[1] = f2tff(v.y * kScale);
        dst[2] = f2tff(v.z * kScale);
        dst[3] = f2tff(v.w * kScale);
    }
    __syncthreads();

    // cache Q fragments in registers (16 k-steps x 4 regs)
    uint32_t qf[16][4];
    const int r0 = wid * 16 + g;
#pragma unroll
    for (int kk = 0; kk < 16; kk++) {
        const float* qp = sm + r0 * 132 + kk * 8 + m4;
        qf[kk][0] = __float_as_uint(qp[0]);
        qf[kk][1] = __float_as_uint(qp[8 * 132]);
        qf[kk][2] = __float_as_uint(qp[4]);
        qf[kk][3] = __float_as_uint(qp[8 * 132 + 4]);
    }
    __syncthreads();

    float mr0 = -1e30f, mr1 = -1e30f, l0 = 0.f, l1 = 0.f;
    float o[16][4];
#pragma unroll
    for (int nd = 0; nd < 16; nd++)
#pragma unroll
        for (int q = 0; q < 4; q++) o[nd][q] = 0.f;

    const float* Kbase = Kg + (size_t)(b * Tv) * EMB + headoff;
    const float* Vbase = Vg + (size_t)(b * Tv) * EMB + headoff;

    for (int j = 0; j < 32; j++) {
        const float* kg = Kbase + (size_t)j * 64 * EMB;
        const float* vg = Vbase + (size_t)j * 64 * EMB;
#pragma unroll
        for (int p = 0; p < 8; p++) {
            int id = tid + 256 * p;
            int r = id >> 5;
            int c = (id & 31) << 2;
            float4 kv = *(const float4*)(kg + (size_t)r * EMB + c);
            float4 vv = *(const float4*)(vg + (size_t)r * EMB + c);
            float* kd = Ks + r * 132 + c;
            kd[0] = f2tff(kv.x); kd[1] = f2tff(kv.y); kd[2] = f2tff(kv.z); kd[3] = f2tff(kv.w);
            float* vd = Vs + r * 132 + c;
            vd[0] = f2tff(vv.x); vd[1] = f2tff(vv.y); vd[2] = f2tff(vv.z); vd[3] = f2tff(vv.w);
        }
        __syncthreads();

        // S = Q K^T (scaled): 16x64 per warp
        float sa[8][4];
#pragma unroll
        for (int ni = 0; ni < 8; ni++)
#pragma unroll
            for (int q = 0; q < 4; q++) sa[ni][q] = 0.f;

#pragma unroll
        for (int kk = 0; kk < 16; kk++) {
#pragma unroll
            for (int ni = 0; ni < 8; ni++) {
                const float* bp = Ks + (ni * 8 + g) * 132 + kk * 8 + m4;
                mma_tf32(sa[ni], qf[kk], __float_as_uint(bp[0]), __float_as_uint(bp[4]));
            }
        }

        // online softmax (rows r0 and r0+8)
        float c0 = -1e30f, c1 = -1e30f;
#pragma unroll
        for (int ni = 0; ni < 8; ni++) {
            c0 = fmaxf(c0, fmaxf(sa[ni][0], sa[ni][1]));
            c1 = fmaxf(c1, fmaxf(sa[ni][2], sa[ni][3]));
        }
        c0 = fmaxf(c0, __shfl_xor_sync(FULLMASK, c0, 1));
        c0 = fmaxf(c0, __shfl_xor_sync(FULLMASK, c0, 2));
        c1 = fmaxf(c1, __shfl_xor_sync(FULLMASK, c1, 1));
        c1 = fmaxf(c1, __shfl_xor_sync(FULLMASK, c1, 2));

        float mn0 = fmaxf(mr0, c0), mn1 = fmaxf(mr1, c1);
        float al0 = exp2f(mr0 - mn0), al1 = exp2f(mr1 - mn1);
        mr0 = mn0; mr1 = mn1;

        float rs0 = 0.f, rs1 = 0.f;
#pragma unroll
        for (int ni = 0; ni < 8; ni++) {
            float p0 = exp2f(sa[ni][0] - mn0);
            float p1 = exp2f(sa[ni][1] - mn0);
            float p2 = exp2f(sa[ni][2] - mn1);
            float p3 = exp2f(sa[ni][3] - mn1);
            rs0 += p0 + p1;
            rs1 += p2 + p3;
            float* pp = Ps + r0 * 68 + ni * 8 + 2 * m4;
            pp[0] = f2tff(p0);
            pp[1] = f2tff(p1);
            pp[8 * 68] = f2tff(p2);
            pp[8 * 68 + 1] = f2tff(p3);
        }
        rs0 += __shfl_xor_sync(FULLMASK, rs0, 1);
        rs0 += __shfl_xor_sync(FULLMASK, rs0, 2);
        rs1 += __shfl_xor_sync(FULLMASK, rs1, 1);
        rs1 += __shfl_xor_sync(FULLMASK, rs1, 2);
        l0 = l0 * al0 + rs0;
        l1 = l1 * al1 + rs1;

#pragma unroll
        for (int nd = 0; nd < 16; nd++) {
            o[nd][0] *= al0; o[nd][1] *= al0;
            o[nd][2] *= al1; o[nd][3] *= al1;
        }
        __syncwarp();  // P rows are per-warp; publish before reading as A fragments

        // O += P @ V
#pragma unroll
        for (int kk = 0; kk < 8; kk++) {
            uint32_t pa[4];
            const float* pp = Ps + r0 * 68 + kk * 8 + m4;
            pa[0] = __float_as_uint(pp[0]);
            pa[1] = __float_as_uint(pp[8 * 68]);
            pa[2] = __float_as_uint(pp[4]);
            pa[3] = __float_as_uint(pp[8 * 68 + 4]);
#pragma unroll
            for (int nd = 0; nd < 16; nd++) {
                const float* vp = Vs + (kk * 8 + m4) * 132 + nd * 8 + g;
                mma_tf32(o[nd], pa, __float_as_uint(vp[0]), __float_as_uint(vp[4 * 132]));
            }
        }
        __syncthreads();  // protect Ks/Vs (and Ps) before next chunk overwrites
    }

    float inv0 = 1.f / l0, inv1 = 1.f / l1;
    size_t row0 = (size_t)(b * Tv) + (size_t)qb * 128 + wid * 16 + g;
    float* Op0 = O + row0 * EMB + headoff;
#pragma unroll
    for (int nd = 0; nd < 16; nd++) {
        int col = nd * 8 + 2 * m4;
        *(float2*)(Op0 + col) = make_float2(o[nd][0] * inv0, o[nd][1] * inv0);
        *(float2*)(Op0 + (size_t)8 * EMB + col) = make_float2(o[nd][2] * inv1, o[nd][3] * inv1);
    }
}

// ---------------- launch ----------------

extern "C" void kernel_launch(void* const* d_in, const int* in_sizes, int n_in,
                              void* d_out, int out_size) {
    const float* x  = (const float*)d_in[0];
    const float* wq = (const float*)d_in[1];
    const float* wk = (const float*)d_in[2];
    const float* wv = (const float*)d_in[3];
    const float* wo = (const float*)d_in[4];
    const float* fc = (const float*)d_in[7];
    const float* fs = (const float*)d_in[8];
    float* out = (float*)d_out;

    float *qb, *kb, *vb, *ob;
    cudaGetSymbolAddress((void**)&qb, g_q);
    cudaGetSymbolAddress((void**)&kb, g_k);
    cudaGetSymbolAddress((void**)&vb, g_v);
    cudaGetSymbolAddress((void**)&ob, g_o);

    const int gemm_smem = 4 * G_STAGE * 4;            // 73728 B
    const int attn_smem = ATT_SMEM_FLOATS * 4;        // 102400 B
    cudaFuncSetAttribute(gemm_nt, cudaFuncAttributeMaxDynamicSharedMemorySize, gemm_smem);
    cudaFuncSetAttribute(attn_kernel, cudaFuncAttributeMaxDynamicSharedMemorySize, attn_smem);

    // fused Q/K/V projections
    dim3 qkv_grid(EMB / 128, Mrows / 128, 3);
    gemm_nt<<<qkv_grid, 256, gemm_smem>>>(x, wq, wk, wv, qb, kb, vb, Mrows, EMB, EMB);

    // RoPE on Q and K
    rope_kernel<<<(Mrows * Hh * 64) / 256, 256>>>(qb, kb, fc, fs);

    // attention
    attn_kernel<<<dim3(Tv / 128, Bv * Hh), 256, attn_smem>>>(qb, kb, vb, ob);

    // output projection
    dim3 o_grid(EMB / 128, Mrows / 128, 1);
    gemm_nt<<<o_grid, 256, gemm_smem>>>(ob, wo, wo, wo, out, out, out, Mrows, EMB, EMB);
}

// round 6
// speedup vs baseline: 1.8004x; 1.8004x over previous
#include <cuda_runtime.h>
#include <cuda_fp16.h>
#include <cstdint>

#define FULLMASK 0xffffffffu

constexpr int Bv    = 2;
constexpr int Tv    = 2048;
constexpr int EMB   = 2048;
constexpr int Hh    = 16;
constexpr int HD    = 128;
constexpr int Mrows = Bv * Tv;  // 4096

// scale folded into Q at rope time: 1/sqrt(HD) * log2(e)
constexpr float QSCALE = 0.08838834764831845f * 1.4426950408889634f;

// -------- scratch (device globals; no allocation allowed) --------
__device__ __half g_xh[Mrows * EMB];
__device__ __half g_wh[4][EMB * EMB];   // wq, wk, wv, wo as fp16
__device__ __half g_qh[Mrows * EMB];
__device__ __half g_kh[Mrows * EMB];
__device__ __half g_vh[Mrows * EMB];
__device__ __half g_oh[Mrows * EMB];

// -------- helpers --------
__device__ __forceinline__ uint32_t h2u(float x, float y) {
    __half2 t = __floats2half2_rn(x, y);
    return *reinterpret_cast<uint32_t*>(&t);
}

__device__ __forceinline__ void cpasync16(uint32_t dst, const void* src) {
    asm volatile("cp.async.cg.shared.global [%0], [%1], 16;" ::"r"(dst), "l"(src));
}

__device__ __forceinline__ void ldsm4(uint32_t& r0, uint32_t& r1, uint32_t& r2, uint32_t& r3,
                                      uint32_t addr) {
    asm volatile("ldmatrix.sync.aligned.m8n8.x4.shared.b16 {%0,%1,%2,%3},[%4];"
                 : "=r"(r0), "=r"(r1), "=r"(r2), "=r"(r3) : "r"(addr));
}
__device__ __forceinline__ void ldsm4t(uint32_t& r0, uint32_t& r1, uint32_t& r2, uint32_t& r3,
                                       uint32_t addr) {
    asm volatile("ldmatrix.sync.aligned.m8n8.x4.trans.shared.b16 {%0,%1,%2,%3},[%4];"
                 : "=r"(r0), "=r"(r1), "=r"(r2), "=r"(r3) : "r"(addr));
}

__device__ __forceinline__ void mma_h(float c[4], const uint32_t a[4], uint32_t b0, uint32_t b1) {
    asm volatile(
        "mma.sync.aligned.m16n8k16.row.col.f32.f16.f16.f32 "
        "{%0,%1,%2,%3},{%4,%5,%6,%7},{%8,%9},{%0,%1,%2,%3};"
        : "+f"(c[0]), "+f"(c[1]), "+f"(c[2]), "+f"(c[3])
        : "r"(a[0]), "r"(a[1]), "r"(a[2]), "r"(a[3]), "r"(b0), "r"(b1));
}

// -------- fp32 -> fp16 convert --------
__global__ void f2h_kernel(const float* __restrict__ s, __half* __restrict__ d, int n4) {
    int i = blockIdx.x * blockDim.x + threadIdx.x;
    if (i >= n4) return;
    float4 v = ((const float4*)s)[i];
    __half2* dp = (__half2*)(d + 4 * (size_t)i);
    dp[0] = __floats2half2_rn(v.x, v.y);
    dp[1] = __floats2half2_rn(v.z, v.w);
}

// -------- GEMM: C[m][n] = sum_k A[m][k] * W[n][k], fp16 in / fp32 acc --------
// BM=128, BN=128, BK=64, 256 threads, 2-stage cp.async, XOR-swizzled smem + ldmatrix.
// qkv_mode=1: half out + fused RoPE on z<2 (z==0 also applies QSCALE).
// qkv_mode=0: fp32 out to Cf.

constexpr int GST = 32768;  // stage bytes (A 16KB + B 16KB)

__global__ __launch_bounds__(256, 2) void gemm_h(
    const __half* __restrict__ A,
    const __half* __restrict__ W0, const __half* __restrict__ W1, const __half* __restrict__ W2,
    __half* __restrict__ H0, __half* __restrict__ H1, __half* __restrict__ H2,
    float* __restrict__ Cf,
    const float* __restrict__ cosv, const float* __restrict__ sinv,
    int qkv_mode, int K, int N) {
    const int z = blockIdx.z;
    const __half* W = (z == 0) ? W0 : (z == 1 ? W1 : W2);
    __half* Hc = (z == 0) ? H0 : (z == 1 ? H1 : H2);

    extern __shared__ char sm[];
    const uint32_t base = (uint32_t)__cvta_generic_to_shared(sm);

    const int tid = threadIdx.x, lane = tid & 31, wid = tid >> 5;
    const int g = lane >> 2, m4 = lane & 3;
    const int wm = wid >> 1, wn = wid & 1;
    const int lr = lane & 7, hb = (lane >> 3) & 1, kh = lane >> 4;
    const int bm = blockIdx.y * 128, bn = blockIdx.x * 128;
    const __half* Ag = A + (size_t)bm * K;
    const __half* Wg = W + (size_t)bn * K;

    float acc[2][8][4];
#pragma unroll
    for (int mi = 0; mi < 2; mi++)
#pragma unroll
        for (int ni = 0; ni < 8; ni++)
#pragma unroll
            for (int q = 0; q < 4; q++) acc[mi][ni][q] = 0.f;

    auto load_stage = [&](int st, int kt) {
        uint32_t ab = base + st * GST;
        uint32_t bb = ab + 16384;
#pragma unroll
        for (int p = 0; p < 4; p++) {
            int id = tid + 256 * p;
            int r = id >> 3, c = id & 7;
            uint32_t off = (uint32_t)r * 128 + (uint32_t)((c ^ (r & 7)) << 4);
            cpasync16(ab + off, Ag + (size_t)r * K + kt + c * 8);
            cpasync16(bb + off, Wg + (size_t)r * K + kt + c * 8);
        }
        asm volatile("cp.async.commit_group;");
    };

    const int NIT = K / 64;
    load_stage(0, 0);

    for (int it = 0; it < NIT; ++it) {
        if (it + 1 < NIT) {
            load_stage((it + 1) & 1, (it + 1) * 64);
            asm volatile("cp.async.wait_group 1;");
        } else {
            asm volatile("cp.async.wait_group 0;");
        }
        __syncthreads();

        uint32_t ab = base + (it & 1) * GST;
        uint32_t bb = ab + 16384;

#pragma unroll
        for (int kk = 0; kk < 4; kk++) {
            uint32_t a[2][4], b[4][4];
#pragma unroll
            for (int mi = 0; mi < 2; mi++) {
                int r = wm * 32 + mi * 16 + lr + hb * 8;
                int ch = kk * 2 + kh;
                ldsm4(a[mi][0], a[mi][1], a[mi][2], a[mi][3],
                      ab + (uint32_t)r * 128 + (uint32_t)((ch ^ (r & 7)) << 4));
            }
#pragma unroll
            for (int ngi = 0; ngi < 4; ngi++) {
                int r = wn * 64 + ngi * 16 + lr + kh * 8;
                int ch = kk * 2 + hb;
                ldsm4(b[ngi][0], b[ngi][1], b[ngi][2], b[ngi][3],
                      bb + (uint32_t)r * 128 + (uint32_t)((ch ^ (r & 7)) << 4));
            }
#pragma unroll
            for (int mi = 0; mi < 2; mi++)
#pragma unroll
                for (int ngi = 0; ngi < 4; ngi++) {
                    mma_h(acc[mi][2 * ngi], a[mi], b[ngi][0], b[ngi][1]);
                    mma_h(acc[mi][2 * ngi + 1], a[mi], b[ngi][2], b[ngi][3]);
                }
        }
        __syncthreads();
    }

    // epilogue (fused RoPE for Q/K in qkv_mode)
#pragma unroll
    for (int mi = 0; mi < 2; mi++) {
        int r0 = bm + wm * 32 + mi * 16 + g;
#pragma unroll
        for (int ni = 0; ni < 8; ni++) {
            int col = bn + wn * 64 + ni * 8 + 2 * m4;
            float v0 = acc[mi][ni][0], v1 = acc[mi][ni][1];
            float v2 = acc[mi][ni][2], v3 = acc[mi][ni][3];
            if (qkv_mode) {
                if (z < 2) {  // RoPE for Q (z=0, with scale) and K (z=1)
                    float scl = (z == 0) ? QSCALE : 1.0f;
                    int d2 = (col & (HD - 1)) >> 1;
                    {
                        int t = r0 & (Tv - 1);
                        float c = cosv[t * 64 + d2], s = sinv[t * 64 + d2];
                        float x = v0, y = v1;
                        v0 = (x * c - y * s) * scl;
                        v1 = (x * s + y * c) * scl;
                    }
                    {
                        int t = (r0 + 8) & (Tv - 1);
                        float c = cosv[t * 64 + d2], s = sinv[t * 64 + d2];
                        float x = v2, y = v3;
                        v2 = (x * c - y * s) * scl;
                        v3 = (x * s + y * c) * scl;
                    }
                }
                *(__half2*)(Hc + (size_t)r0 * N + col) = __floats2half2_rn(v0, v1);
                *(__half2*)(Hc + (size_t)(r0 + 8) * N + col) = __floats2half2_rn(v2, v3);
            } else {
                *(float2*)(Cf + (size_t)r0 * N + col) = make_float2(v0, v1);
                *(float2*)(Cf + (size_t)(r0 + 8) * N + col) = make_float2(v2, v3);
            }
        }
    }
}

// -------- Flash attention (non-causal), fp16 mma --------
// Br=128 (8 warps x 16 rows), Bc=64, HD=128.
// smem 64KB: Q staging 32KB (reused), then KV double-buffer 2x(K 16KB + V 16KB).
// P converted C-frag -> A-frag in registers (no smem roundtrip).

__global__ __launch_bounds__(256, 1) void attn_h(
    const __half* __restrict__ Q, const __half* __restrict__ Kg,
    const __half* __restrict__ Vg, __half* __restrict__ O) {
    extern __shared__ char sm[];
    const uint32_t base = (uint32_t)__cvta_generic_to_shared(sm);

    const int tid = threadIdx.x, lane = tid & 31, wid = tid >> 5;
    const int g = lane >> 2, m4 = lane & 3;
    const int lr = lane & 7, hb = (lane >> 3) & 1, kh = lane >> 4;
    const int qb = blockIdx.x;
    const int b = blockIdx.y >> 4, h = blockIdx.y & 15;

    const __half* Qg = Q + ((size_t)(b * Tv) + (size_t)qb * 128) * EMB + h * HD;
    const __half* Kb = Kg + (size_t)(b * Tv) * EMB + h * HD;
    const __half* Vb = Vg + (size_t)(b * Tv) * EMB + h * HD;

    // stage Q tile (rows of 128 halves = 16 chunks, XOR swizzle)
#pragma unroll
    for (int p = 0; p < 8; p++) {
        int id = tid + 256 * p;
        int r = id >> 4, c = id & 15;
        cpasync16(base + (uint32_t)r * 256 + (uint32_t)((c ^ (r & 7)) << 4),
                  Qg + (size_t)r * EMB + c * 8);
    }
    asm volatile("cp.async.commit_group;");
    asm volatile("cp.async.wait_group 0;");
    __syncthreads();

    // Q fragments in registers: 8 k-steps x 4 regs
    uint32_t qf[8][4];
#pragma unroll
    for (int kk = 0; kk < 8; kk++) {
        int r = wid * 16 + lr + hb * 8;
        int ch = kk * 2 + kh;
        ldsm4(qf[kk][0], qf[kk][1], qf[kk][2], qf[kk][3],
              base + (uint32_t)r * 256 + (uint32_t)((ch ^ (r & 7)) << 4));
    }
    __syncthreads();  // all warps done reading Q before KV overwrites region

    float mr0 = -1e30f, mr1 = -1e30f, l0 = 0.f, l1 = 0.f;
    float o[16][4];
#pragma unroll
    for (int nd = 0; nd < 16; nd++)
#pragma unroll
        for (int q = 0; q < 4; q++) o[nd][q] = 0.f;

    auto load_kv = [&](int j, int st) {
        uint32_t kb = base + (uint32_t)st * 32768;
        uint32_t vb = kb + 16384;
        const __half* kg = Kb + (size_t)j * 64 * EMB;
        const __half* vg = Vb + (size_t)j * 64 * EMB;
#pragma unroll
        for (int p = 0; p < 4; p++) {
            int id = tid + 256 * p;
            int r = id >> 4, c = id & 15;
            uint32_t off = (uint32_t)r * 256 + (uint32_t)((c ^ (r & 7)) << 4);
            cpasync16(kb + off, kg + (size_t)r * EMB + c * 8);
            cpasync16(vb + off, vg + (size_t)r * EMB + c * 8);
        }
        asm volatile("cp.async.commit_group;");
    };

    load_kv(0, 0);

    for (int j = 0; j < 32; j++) {
        if (j + 1 < 32) {
            load_kv(j + 1, (j + 1) & 1);
            asm volatile("cp.async.wait_group 1;");
        } else {
            asm volatile("cp.async.wait_group 0;");
        }
        __syncthreads();

        uint32_t kb = base + (uint32_t)(j & 1) * 32768;
        uint32_t vb = kb + 16384;

        // S = Q K^T (scale pre-folded into Q)
        float sa[8][4];
#pragma unroll
        for (int ni = 0; ni < 8; ni++)
#pragma unroll
            for (int q = 0; q < 4; q++) sa[ni][q] = 0.f;

#pragma unroll
        for (int kk = 0; kk < 8; kk++) {
            uint32_t bf[4][4];
#pragma unroll
            for (int ngi = 0; ngi < 4; ngi++) {
                int r = ngi * 16 + lr + kh * 8;
                int ch = kk * 2 + hb;
                ldsm4(bf[ngi][0], bf[ngi][1], bf[ngi][2], bf[ngi][3],
                      kb + (uint32_t)r * 256 + (uint32_t)((ch ^ (r & 7)) << 4));
            }
#pragma unroll
            for (int ngi = 0; ngi < 4; ngi++) {
                mma_h(sa[2 * ngi], qf[kk], bf[ngi][0], bf[ngi][1]);
                mma_h(sa[2 * ngi + 1], qf[kk], bf[ngi][2], bf[ngi][3]);
            }
        }

        // online softmax (rows g and g+8), base-2 domain
        float c0 = -1e30f, c1 = -1e30f;
#pragma unroll
        for (int ni = 0; ni < 8; ni++) {
            c0 = fmaxf(c0, fmaxf(sa[ni][0], sa[ni][1]));
            c1 = fmaxf(c1, fmaxf(sa[ni][2], sa[ni][3]));
        }
        c0 = fmaxf(c0, __shfl_xor_sync(FULLMASK, c0, 1));
        c0 = fmaxf(c0, __shfl_xor_sync(FULLMASK, c0, 2));
        c1 = fmaxf(c1, __shfl_xor_sync(FULLMASK, c1, 1));
        c1 = fmaxf(c1, __shfl_xor_sync(FULLMASK, c1, 2));

        float mn0 = fmaxf(mr0, c0), mn1 = fmaxf(mr1, c1);
        float al0 = exp2f(mr0 - mn0), al1 = exp2f(mr1 - mn1);
        mr0 = mn0; mr1 = mn1;

        float rs0 = 0.f, rs1 = 0.f;
#pragma unroll
        for (int ni = 0; ni < 8; ni++) {
            sa[ni][0] = exp2f(sa[ni][0] - mn0);
            sa[ni][1] = exp2f(sa[ni][1] - mn0);
            sa[ni][2] = exp2f(sa[ni][2] - mn1);
            sa[ni][3] = exp2f(sa[ni][3] - mn1);
            rs0 += sa[ni][0] + sa[ni][1];
            rs1 += sa[ni][2] + sa[ni][3];
        }
        rs0 += __shfl_xor_sync(FULLMASK, rs0, 1);
        rs0 += __shfl_xor_sync(FULLMASK, rs0, 2);
        rs1 += __shfl_xor_sync(FULLMASK, rs1, 1);
        rs1 += __shfl_xor_sync(FULLMASK, rs1, 2);
        l0 = l0 * al0 + rs0;
        l1 = l1 * al1 + rs1;

#pragma unroll
        for (int nd = 0; nd < 16; nd++) {
            o[nd][0] *= al0; o[nd][1] *= al0;
            o[nd][2] *= al1; o[nd][3] *= al1;
        }

        // O += P @ V ; P C-frag -> A-frag packed in registers
#pragma unroll
        for (int kk2 = 0; kk2 < 4; kk2++) {
            uint32_t pa[4];
            pa[0] = h2u(sa[2 * kk2][0], sa[2 * kk2][1]);
            pa[1] = h2u(sa[2 * kk2][2], sa[2 * kk2][3]);
            pa[2] = h2u(sa[2 * kk2 + 1][0], sa[2 * kk2 + 1][1]);
            pa[3] = h2u(sa[2 * kk2 + 1][2], sa[2 * kk2 + 1][3]);
            int r = kk2 * 16 + lr + hb * 8;
#pragma unroll
            for (int ndg = 0; ndg < 8; ndg++) {
                int ch = ndg * 2 + kh;
                uint32_t v0, v1, v2, v3;
                ldsm4t(v0, v1, v2, v3,
                       vb + (uint32_t)r * 256 + (uint32_t)((ch ^ (r & 7)) << 4));
                mma_h(o[2 * ndg], pa, v0, v1);
                mma_h(o[2 * ndg + 1], pa, v2, v3);
            }
        }
        __syncthreads();  // stage j free before prefetch of j+2
    }

    float inv0 = 1.f / l0, inv1 = 1.f / l1;
    size_t row0 = (size_t)(b * Tv) + (size_t)qb * 128 + wid * 16 + g;
    __half* Op = O + row0 * EMB + h * HD;
#pragma unroll
    for (int nd = 0; nd < 16; nd++) {
        int col = nd * 8 + 2 * m4;
        *(__half2*)(Op + col) = __floats2half2_rn(o[nd][0] * inv0, o[nd][1] * inv0);
        *(__half2*)(Op + (size_t)8 * EMB + col) = __floats2half2_rn(o[nd][2] * inv1, o[nd][3] * inv1);
    }
}

// -------- launch --------
extern "C" void kernel_launch(void* const* d_in, const int* in_sizes, int n_in,
                              void* d_out, int out_size) {
    const float* x  = (const float*)d_in[0];
    const float* wq = (const float*)d_in[1];
    const float* wk = (const float*)d_in[2];
    const float* wv = (const float*)d_in[3];
    const float* wo = (const float*)d_in[4];
    const float* fc = (const float*)d_in[7];
    const float* fs = (const float*)d_in[8];
    float* out = (float*)d_out;

    __half *xh, *wh, *qh, *kh, *vh, *oh;
    cudaGetSymbolAddress((void**)&xh, g_xh);
    cudaGetSymbolAddress((void**)&wh, g_wh);
    cudaGetSymbolAddress((void**)&qh, g_qh);
    cudaGetSymbolAddress((void**)&kh, g_kh);
    cudaGetSymbolAddress((void**)&vh, g_vh);
    cudaGetSymbolAddress((void**)&oh, g_oh);
    __half* wqh = wh;
    __half* wkh = wh + (size_t)EMB * EMB;
    __half* wvh = wh + 2 * (size_t)EMB * EMB;
    __half* woh = wh + 3 * (size_t)EMB * EMB;

    const int smem = 65536;
    cudaFuncSetAttribute(gemm_h, cudaFuncAttributeMaxDynamicSharedMemorySize, smem);
    cudaFuncSetAttribute(attn_h, cudaFuncAttributeMaxDynamicSharedMemorySize, smem);

    // fp32 -> fp16 converts
    f2h_kernel<<<(Mrows * EMB / 4) / 256, 256>>>(x, xh, Mrows * EMB / 4);
    f2h_kernel<<<(EMB * EMB / 4) / 256, 256>>>(wq, wqh, EMB * EMB / 4);
    f2h_kernel<<<(EMB * EMB / 4) / 256, 256>>>(wk, wkh, EMB * EMB / 4);
    f2h_kernel<<<(EMB * EMB / 4) / 256, 256>>>(wv, wvh, EMB * EMB / 4);
    f2h_kernel<<<(EMB * EMB / 4) / 256, 256>>>(wo, woh, EMB * EMB / 4);

    // fused QKV projection + RoPE (+softmax scale on Q) in epilogue
    gemm_h<<<dim3(EMB / 128, Mrows / 128, 3), 256, smem>>>(
        xh, wqh, wkh, wvh, qh, kh, vh, nullptr, fc, fs, 1, EMB, EMB);

    // flash attention
    attn_h<<<dim3(Tv / 128, Bv * Hh), 256, smem>>>(qh, kh, vh, oh);

    // output projection (fp32 out)
    gemm_h<<<dim3(EMB / 128, Mrows / 128, 1), 256, smem>>>(
        oh, woh, woh, woh, nullptr, nullptr, nullptr, out, nullptr, nullptr, 0, EMB, EMB);
}

// round 9
// speedup vs baseline: 2.6163x; 1.4532x over previous
#include <cuda_runtime.h>
#include <cuda_fp16.h>
#include <cstdint>

#define FULLMASK 0xffffffffu

constexpr int Bv    = 2;
constexpr int Tv    = 2048;
constexpr int EMB   = 2048;
constexpr int Hh    = 16;
constexpr int HD    = 128;
constexpr int Mrows = Bv * Tv;  // 4096

// scale folded into Q at rope time: 1/sqrt(HD) * log2(e)
constexpr float QSCALE = 0.08838834764831845f * 1.4426950408889634f;

// -------- scratch (device globals; no allocation allowed) --------
__device__ __align__(256) __half g_xh[Mrows * EMB];
__device__ __align__(256) __half g_wh[4][EMB * EMB];   // wq, wk, wv, wo as fp16
__device__ __align__(256) __half g_qh[Mrows * EMB];
__device__ __align__(256) __half g_kh[Mrows * EMB];
__device__ __align__(256) __half g_vh[Mrows * EMB];
__device__ __align__(256) __half g_oh[Mrows * EMB];

// -------- helpers --------
__device__ __forceinline__ uint32_t h2u(float x, float y) {
    __half2 t = __floats2half2_rn(x, y);
    return *reinterpret_cast<uint32_t*>(&t);
}
__device__ __forceinline__ void cpasync16(uint32_t dst, const void* src) {
    asm volatile("cp.async.cg.shared.global [%0], [%1], 16;" ::"r"(dst), "l"(src));
}
__device__ __forceinline__ void ldsm4(uint32_t& r0, uint32_t& r1, uint32_t& r2, uint32_t& r3,
                                      uint32_t addr) {
    asm volatile("ldmatrix.sync.aligned.m8n8.x4.shared.b16 {%0,%1,%2,%3},[%4];"
                 : "=r"(r0), "=r"(r1), "=r"(r2), "=r"(r3) : "r"(addr));
}
__device__ __forceinline__ void ldsm4t(uint32_t& r0, uint32_t& r1, uint32_t& r2, uint32_t& r3,
                                       uint32_t addr) {
    asm volatile("ldmatrix.sync.aligned.m8n8.x4.trans.shared.b16 {%0,%1,%2,%3},[%4];"
                 : "=r"(r0), "=r"(r1), "=r"(r2), "=r"(r3) : "r"(addr));
}
__device__ __forceinline__ void mma_h(float c[4], const uint32_t a[4], uint32_t b0, uint32_t b1) {
    asm volatile(
        "mma.sync.aligned.m16n8k16.row.col.f32.f16.f16.f32 "
        "{%0,%1,%2,%3},{%4,%5,%6,%7},{%8,%9},{%0,%1,%2,%3};"
        : "+f"(c[0]), "+f"(c[1]), "+f"(c[2]), "+f"(c[3])
        : "r"(a[0]), "r"(a[1]), "r"(a[2]), "r"(a[3]), "r"(b0), "r"(b1));
}

// -------- fp32 -> fp16 convert, all 5 tensors in one launch --------
__global__ void f2h_all(const float* __restrict__ x,
                        const float* __restrict__ wq, const float* __restrict__ wk,
                        const float* __restrict__ wv, const float* __restrict__ wo,
                        __half* __restrict__ xh, __half* __restrict__ wh) {
    const int seg = blockIdx.y;
    const float* s;
    __half* d;
    int n4;
    if (seg == 0) {
        s = x; d = xh; n4 = Mrows * EMB / 4;
    } else {
        const float* ws[4] = {wq, wk, wv, wo};
        s = ws[seg - 1];
        d = wh + (size_t)(seg - 1) * EMB * EMB;
        n4 = EMB * EMB / 4;
    }
    int i = blockIdx.x * blockDim.x + threadIdx.x;
    if (i >= n4) return;
    float4 v = ((const float4*)s)[i];
    __half2* dp = (__half2*)(d + 4 * (size_t)i);
    dp[0] = __floats2half2_rn(v.x, v.y);
    dp[1] = __floats2half2_rn(v.z, v.w);
}

// -------- GEMM: C[m][n] = sum_k A[m][k] * W[n][k], fp16 in / fp32 acc --------
// BM=128, BN=128, BK=64, 256 threads, 3-stage cp.async ring, ONE sync/iter,
// XOR-swizzled smem + ldmatrix.
// qkv_mode=1: half out + fused RoPE on z<2 (z==0 also applies QSCALE).
// qkv_mode=0: fp32 out to Cf.

constexpr int GST = 32768;  // stage bytes (A 16KB + B 16KB)
constexpr int GEMM_SMEM = 3 * GST;  // 98304

__global__ __launch_bounds__(256, 2) void gemm_h(
    const __half* __restrict__ A,
    const __half* __restrict__ W0, const __half* __restrict__ W1, const __half* __restrict__ W2,
    __half* __restrict__ H0, __half* __restrict__ H1, __half* __restrict__ H2,
    float* __restrict__ Cf,
    const float* __restrict__ cosv, const float* __restrict__ sinv,
    int qkv_mode, int K, int N) {
    const int z = blockIdx.z;
    const __half* W = (z == 0) ? W0 : (z == 1 ? W1 : W2);
    __half* Hc = (z == 0) ? H0 : (z == 1 ? H1 : H2);

    extern __shared__ char sm[];
    const uint32_t base = (uint32_t)__cvta_generic_to_shared(sm);

    const int tid = threadIdx.x, lane = tid & 31, wid = tid >> 5;
    const int g = lane >> 2, m4 = lane & 3;
    const int wm = wid >> 1, wn = wid & 1;
    const int lr = lane & 7, hb = (lane >> 3) & 1, kh = lane >> 4;
    const int bm = blockIdx.y * 128, bn = blockIdx.x * 128;
    const __half* Ag = A + (size_t)bm * K;
    const __half* Wg = W + (size_t)bn * K;

    float acc[2][8][4];
#pragma unroll
    for (int mi = 0; mi < 2; mi++)
#pragma unroll
        for (int ni = 0; ni < 8; ni++)
#pragma unroll
            for (int q = 0; q < 4; q++) acc[mi][ni][q] = 0.f;

    auto load_stage = [&](int st, int kt) {
        uint32_t ab = base + (uint32_t)st * GST;
        uint32_t bb = ab + 16384;
#pragma unroll
        for (int p = 0; p < 4; p++) {
            int id = tid + 256 * p;
            int r = id >> 3, c = id & 7;
            uint32_t off = (uint32_t)r * 128 + (uint32_t)((c ^ (r & 7)) << 4);
            cpasync16(ab + off, Ag + (size_t)r * K + kt + c * 8);
            cpasync16(bb + off, Wg + (size_t)r * K + kt + c * 8);
        }
        asm volatile("cp.async.commit_group;");
    };

    const int NIT = K / 64;  // 32
    load_stage(0, 0);
    load_stage(1, 64);

    for (int it = 0; it < NIT; ++it) {
        if (it < NIT - 1) asm volatile("cp.async.wait_group 1;");
        else              asm volatile("cp.async.wait_group 0;");
        __syncthreads();
        // sync proves all warps finished compute(it-1); stage (it+2)%3 == (it-1)%3 is free
        if (it + 2 < NIT) load_stage((it + 2) % 3, (it + 2) * 64);

        uint32_t ab = base + (uint32_t)(it % 3) * GST;
        uint32_t bb = ab + 16384;

#pragma unroll
        for (int kk = 0; kk < 4; kk++) {
            uint32_t a[2][4], b[4][4];
#pragma unroll
            for (int mi = 0; mi < 2; mi++) {
                int r = wm * 32 + mi * 16 + lr + hb * 8;
                int ch = kk * 2 + kh;
                ldsm4(a[mi][0], a[mi][1], a[mi][2], a[mi][3],
                      ab + (uint32_t)r * 128 + (uint32_t)((ch ^ (r & 7)) << 4));
            }
#pragma unroll
            for (int ngi = 0; ngi < 4; ngi++) {
                int r = wn * 64 + ngi * 16 + lr + kh * 8;
                int ch = kk * 2 + hb;
                ldsm4(b[ngi][0], b[ngi][1], b[ngi][2], b[ngi][3],
                      bb + (uint32_t)r * 128 + (uint32_t)((ch ^ (r & 7)) << 4));
            }
#pragma unroll
            for (int mi = 0; mi < 2; mi++)
#pragma unroll
                for (int ngi = 0; ngi < 4; ngi++) {
                    mma_h(acc[mi][2 * ngi], a[mi], b[ngi][0], b[ngi][1]);
                    mma_h(acc[mi][2 * ngi + 1], a[mi], b[ngi][2], b[ngi][3]);
                }
        }
    }

    // epilogue (fused RoPE for Q/K in qkv_mode)
#pragma unroll
    for (int mi = 0; mi < 2; mi++) {
        int r0 = bm + wm * 32 + mi * 16 + g;
#pragma unroll
        for (int ni = 0; ni < 8; ni++) {
            int col = bn + wn * 64 + ni * 8 + 2 * m4;
            float v0 = acc[mi][ni][0], v1 = acc[mi][ni][1];
            float v2 = acc[mi][ni][2], v3 = acc[mi][ni][3];
            if (qkv_mode) {
                if (z < 2) {  // RoPE for Q (z=0, with scale) and K (z=1)
                    float scl = (z == 0) ? QSCALE : 1.0f;
                    int d2 = (col & (HD - 1)) >> 1;
                    {
                        int t = r0 & (Tv - 1);
                        float c = cosv[t * 64 + d2], s = sinv[t * 64 + d2];
                        float xx = v0, yy = v1;
                        v0 = (xx * c - yy * s) * scl;
                        v1 = (xx * s + yy * c) * scl;
                    }
                    {
                        int t = (r0 + 8) & (Tv - 1);
                        float c = cosv[t * 64 + d2], s = sinv[t * 64 + d2];
                        float xx = v2, yy = v3;
                        v2 = (xx * c - yy * s) * scl;
                        v3 = (xx * s + yy * c) * scl;
                    }
                }
                *(__half2*)(Hc + (size_t)r0 * N + col) = __floats2half2_rn(v0, v1);
                *(__half2*)(Hc + (size_t)(r0 + 8) * N + col) = __floats2half2_rn(v2, v3);
            } else {
                *(float2*)(Cf + (size_t)r0 * N + col) = make_float2(v0, v1);
                *(float2*)(Cf + (size_t)(r0 + 8) * N + col) = make_float2(v2, v3);
            }
        }
    }
}

// -------- Flash attention (non-causal), fp16 mma.sync --------
// Br=128 (8 warps x 16 rows), Bc=64, HD=128.
// 3-stage KV ring (32KB/stage), ONE sync per iteration.
// P converted C-frag -> A-frag in registers (no smem roundtrip).

constexpr int ATT_SMEM = 3 * 32768;  // 98304

__global__ __launch_bounds__(256, 1) void attn_h(
    const __half* __restrict__ Q, const __half* __restrict__ Kg,
    const __half* __restrict__ Vg, __half* __restrict__ O) {
    extern __shared__ char sm[];
    const uint32_t base = (uint32_t)__cvta_generic_to_shared(sm);

    const int tid = threadIdx.x, lane = tid & 31, wid = tid >> 5;
    const int g = lane >> 2, m4 = lane & 3;
    const int lr = lane & 7, hb = (lane >> 3) & 1, kh = lane >> 4;
    const int qb = blockIdx.x;
    const int b = blockIdx.y >> 4, h = blockIdx.y & 15;

    const __half* Qg = Q + ((size_t)(b * Tv) + (size_t)qb * 128) * EMB + h * HD;
    const __half* Kb = Kg + (size_t)(b * Tv) * EMB + h * HD;
    const __half* Vb = Vg + (size_t)(b * Tv) * EMB + h * HD;

    // stage Q tile into stage-0 region (rows of 128 halves, XOR swizzle)
#pragma unroll
    for (int p = 0; p < 8; p++) {
        int id = tid + 256 * p;
        int r = id >> 4, c = id & 15;
        cpasync16(base + (uint32_t)r * 256 + (uint32_t)((c ^ (r & 7)) << 4),
                  Qg + (size_t)r * EMB + c * 8);
    }
    asm volatile("cp.async.commit_group;");
    asm volatile("cp.async.wait_group 0;");
    __syncthreads();

    // Q fragments in registers: 8 k-steps x 4 regs
    uint32_t qf[8][4];
#pragma unroll
    for (int kk = 0; kk < 8; kk++) {
        int r = wid * 16 + lr + hb * 8;
        int ch = kk * 2 + kh;
        ldsm4(qf[kk][0], qf[kk][1], qf[kk][2], qf[kk][3],
              base + (uint32_t)r * 256 + (uint32_t)((ch ^ (r & 7)) << 4));
    }
    __syncthreads();  // all warps done reading Q before KV overwrites stage 0

    float mr0 = -1e30f, mr1 = -1e30f, l0 = 0.f, l1 = 0.f;
    float o[16][4];
#pragma unroll
    for (int nd = 0; nd < 16; nd++)
#pragma unroll
        for (int q = 0; q < 4; q++) o[nd][q] = 0.f;

    auto load_kv = [&](int j, int st) {
        uint32_t kb = base + (uint32_t)st * 32768;
        uint32_t vb = kb + 16384;
        const __half* kg = Kb + (size_t)j * 64 * EMB;
        const __half* vg = Vb + (size_t)j * 64 * EMB;
#pragma unroll
        for (int p = 0; p < 4; p++) {
            int id = tid + 256 * p;
            int r = id >> 4, c = id & 15;
            uint32_t off = (uint32_t)r * 256 + (uint32_t)((c ^ (r & 7)) << 4);
            cpasync16(kb + off, kg + (size_t)r * EMB + c * 8);
            cpasync16(vb + off, vg + (size_t)r * EMB + c * 8);
        }
        asm volatile("cp.async.commit_group;");
    };

    load_kv(0, 0);
    load_kv(1, 1);

    for (int j = 0; j < 32; j++) {
        if (j < 31) asm volatile("cp.async.wait_group 1;");
        else        asm volatile("cp.async.wait_group 0;");
        __syncthreads();
        // stage (j+2)%3 == (j-1)%3, finished by all warps at this sync
        if (j + 2 < 32) load_kv(j + 2, (j + 2) % 3);

        uint32_t kb = base + (uint32_t)(j % 3) * 32768;
        uint32_t vb = kb + 16384;

        // S = Q K^T (scale pre-folded into Q)
        float sa[8][4];
#pragma unroll
        for (int ni = 0; ni < 8; ni++)
#pragma unroll
            for (int q = 0; q < 4; q++) sa[ni][q] = 0.f;

#pragma unroll
        for (int kk = 0; kk < 8; kk++) {
            uint32_t bf[4][4];
#pragma unroll
            for (int ngi = 0; ngi < 4; ngi++) {
                int r = ngi * 16 + lr + kh * 8;
                int ch = kk * 2 + hb;
                ldsm4(bf[ngi][0], bf[ngi][1], bf[ngi][2], bf[ngi][3],
                      kb + (uint32_t)r * 256 + (uint32_t)((ch ^ (r & 7)) << 4));
            }
#pragma unroll
            for (int ngi = 0; ngi < 4; ngi++) {
                mma_h(sa[2 * ngi], qf[kk], bf[ngi][0], bf[ngi][1]);
                mma_h(sa[2 * ngi + 1], qf[kk], bf[ngi][2], bf[ngi][3]);
            }
        }

        // online softmax (rows g and g+8), base-2 domain
        float c0 = -1e30f, c1 = -1e30f;
#pragma unroll
        for (int ni = 0; ni < 8; ni++) {
            c0 = fmaxf(c0, fmaxf(sa[ni][0], sa[ni][1]));
            c1 = fmaxf(c1, fmaxf(sa[ni][2], sa[ni][3]));
        }
        c0 = fmaxf(c0, __shfl_xor_sync(FULLMASK, c0, 1));
        c0 = fmaxf(c0, __shfl_xor_sync(FULLMASK, c0, 2));
        c1 = fmaxf(c1, __shfl_xor_sync(FULLMASK, c1, 1));
        c1 = fmaxf(c1, __shfl_xor_sync(FULLMASK, c1, 2));

        float mn0 = fmaxf(mr0, c0), mn1 = fmaxf(mr1, c1);
        float al0 = exp2f(mr0 - mn0), al1 = exp2f(mr1 - mn1);
        mr0 = mn0; mr1 = mn1;

        float rs0 = 0.f, rs1 = 0.f;
#pragma unroll
        for (int ni = 0; ni < 8; ni++) {
            sa[ni][0] = exp2f(sa[ni][0] - mn0);
            sa[ni][1] = exp2f(sa[ni][1] - mn0);
            sa[ni][2] = exp2f(sa[ni][2] - mn1);
            sa[ni][3] = exp2f(sa[ni][3] - mn1);
            rs0 += sa[ni][0] + sa[ni][1];
            rs1 += sa[ni][2] + sa[ni][3];
        }
        rs0 += __shfl_xor_sync(FULLMASK, rs0, 1);
        rs0 += __shfl_xor_sync(FULLMASK, rs0, 2);
        rs1 += __shfl_xor_sync(FULLMASK, rs1, 1);
        rs1 += __shfl_xor_sync(FULLMASK, rs1, 2);
        l0 = l0 * al0 + rs0;
        l1 = l1 * al1 + rs1;

#pragma unroll
        for (int nd = 0; nd < 16; nd++) {
            o[nd][0] *= al0; o[nd][1] *= al0;
            o[nd][2] *= al1; o[nd][3] *= al1;
        }

        // O += P @ V ; P C-frag -> A-frag packed in registers
#pragma unroll
        for (int kk2 = 0; kk2 < 4; kk2++) {
            uint32_t pa[4];
            pa[0] = h2u(sa[2 * kk2][0], sa[2 * kk2][1]);
            pa[1] = h2u(sa[2 * kk2][2], sa[2 * kk2][3]);
            pa[2] = h2u(sa[2 * kk2 + 1][0], sa[2 * kk2 + 1][1]);
            pa[3] = h2u(sa[2 * kk2 + 1][2], sa[2 * kk2 + 1][3]);
            int r = kk2 * 16 + lr + hb * 8;
#pragma unroll
            for (int ndg = 0; ndg < 8; ndg++) {
                int ch = ndg * 2 + kh;
                uint32_t v0, v1, v2, v3;
                ldsm4t(v0, v1, v2, v3,
                       vb + (uint32_t)r * 256 + (uint32_t)((ch ^ (r & 7)) << 4));
                mma_h(o[2 * ndg], pa, v0, v1);
                mma_h(o[2 * ndg + 1], pa, v2, v3);
            }
        }
    }

    float inv0 = 1.f / l0, inv1 = 1.f / l1;
    size_t row0 = (size_t)(b * Tv) + (size_t)qb * 128 + wid * 16 + g;
    __half* Op = O + row0 * EMB + h * HD;
#pragma unroll
    for (int nd = 0; nd < 16; nd++) {
        int col = nd * 8 + 2 * m4;
        *(__half2*)(Op + col) = __floats2half2_rn(o[nd][0] * inv0, o[nd][1] * inv0);
        *(__half2*)(Op + (size_t)8 * EMB + col) = __floats2half2_rn(o[nd][2] * inv1, o[nd][3] * inv1);
    }
}

// -------- launch --------
extern "C" void kernel_launch(void* const* d_in, const int* in_sizes, int n_in,
                              void* d_out, int out_size) {
    const float* x  = (const float*)d_in[0];
    const float* wq = (const float*)d_in[1];
    const float* wk = (const float*)d_in[2];
    const float* wv = (const float*)d_in[3];
    const float* wo = (const float*)d_in[4];
    const float* fc = (const float*)d_in[7];
    const float* fs = (const float*)d_in[8];
    float* out = (float*)d_out;

    __half *xh, *wh, *qh, *kh, *vh, *oh;
    cudaGetSymbolAddress((void**)&xh, g_xh);
    cudaGetSymbolAddress((void**)&wh, g_wh);
    cudaGetSymbolAddress((void**)&qh, g_qh);
    cudaGetSymbolAddress((void**)&kh, g_kh);
    cudaGetSymbolAddress((void**)&vh, g_vh);
    cudaGetSymbolAddress((void**)&oh, g_oh);
    __half* wqh = wh;
    __half* wkh = wh + (size_t)EMB * EMB;
    __half* wvh = wh + 2 * (size_t)EMB * EMB;
    __half* woh = wh + 3 * (size_t)EMB * EMB;

    cudaFuncSetAttribute(gemm_h, cudaFuncAttributeMaxDynamicSharedMemorySize, GEMM_SMEM);
    cudaFuncSetAttribute(attn_h, cudaFuncAttributeMaxDynamicSharedMemorySize, ATT_SMEM);

    // fp32 -> fp16 converts (one launch, 5 segments)
    f2h_all<<<dim3(Mrows * EMB / 4 / 256, 5), 256>>>(x, wq, wk, wv, wo, xh, wh);

    // fused QKV projection + RoPE (+softmax scale on Q) in epilogue
    gemm_h<<<dim3(EMB / 128, Mrows / 128, 3), 256, GEMM_SMEM>>>(
        xh, wqh, wkh, wvh, qh, kh, vh, nullptr, fc, fs, 1, EMB, EMB);

    // flash attention
    attn_h<<<dim3(Tv / 128, Bv * Hh), 256, ATT_SMEM>>>(qh, kh, vh, oh);

    // output projection (fp32 out)
    gemm_h<<<dim3(EMB / 128, Mrows / 128, 1), 256, GEMM_SMEM>>>(
        oh, woh, woh, woh, nullptr, nullptr, nullptr, out, nullptr, nullptr, 0, EMB, EMB);
}

// round 10
// speedup vs baseline: 2.7025x; 1.0329x over previous
#include <cuda_runtime.h>
#include <cuda_fp16.h>
#include <cstdint>

#define FULLMASK 0xffffffffu

constexpr int Bv    = 2;
constexpr int Tv    = 2048;
constexpr int EMB   = 2048;
constexpr int Hh    = 16;
constexpr int HD    = 128;
constexpr int Mrows = Bv * Tv;  // 4096

// scale folded into Q at rope time: 1/sqrt(HD) * log2(e)
constexpr float QSCALE = 0.08838834764831845f * 1.4426950408889634f;

// -------- scratch (device globals; no allocation allowed) --------
__device__ __align__(256) __half g_xh[Mrows * EMB];
__device__ __align__(256) __half g_wh[4][EMB * EMB];   // wq, wk, wv, wo as fp16
__device__ __align__(256) __half g_qh[Mrows * EMB];
__device__ __align__(256) __half g_kh[Mrows * EMB];
__device__ __align__(256) __half g_vh[Mrows * EMB];
__device__ __align__(256) __half g_oh[Mrows * EMB];

// -------- helpers --------
__device__ __forceinline__ uint32_t h2u(float x, float y) {
    __half2 t = __floats2half2_rn(x, y);
    return *reinterpret_cast<uint32_t*>(&t);
}
__device__ __forceinline__ void cpasync16(uint32_t dst, const void* src) {
    asm volatile("cp.async.cg.shared.global [%0], [%1], 16;" ::"r"(dst), "l"(src));
}
__device__ __forceinline__ void ldsm4(uint32_t& r0, uint32_t& r1, uint32_t& r2, uint32_t& r3,
                                      uint32_t addr) {
    asm volatile("ldmatrix.sync.aligned.m8n8.x4.shared.b16 {%0,%1,%2,%3},[%4];"
                 : "=r"(r0), "=r"(r1), "=r"(r2), "=r"(r3) : "r"(addr));
}
__device__ __forceinline__ void ldsm4t(uint32_t& r0, uint32_t& r1, uint32_t& r2, uint32_t& r3,
                                       uint32_t addr) {
    asm volatile("ldmatrix.sync.aligned.m8n8.x4.trans.shared.b16 {%0,%1,%2,%3},[%4];"
                 : "=r"(r0), "=r"(r1), "=r"(r2), "=r"(r3) : "r"(addr));
}
__device__ __forceinline__ void mma_h(float c[4], const uint32_t a[4], uint32_t b0, uint32_t b1) {
    asm volatile(
        "mma.sync.aligned.m16n8k16.row.col.f32.f16.f16.f32 "
        "{%0,%1,%2,%3},{%4,%5,%6,%7},{%8,%9},{%0,%1,%2,%3};"
        : "+f"(c[0]), "+f"(c[1]), "+f"(c[2]), "+f"(c[3])
        : "r"(a[0]), "r"(a[1]), "r"(a[2]), "r"(a[3]), "r"(b0), "r"(b1));
}

// -------- fp32 -> fp16 convert, all 5 tensors in one launch --------
__global__ void f2h_all(const float* __restrict__ x,
                        const float* __restrict__ wq, const float* __restrict__ wk,
                        const float* __restrict__ wv, const float* __restrict__ wo,
                        __half* __restrict__ xh, __half* __restrict__ wh) {
    const int seg = blockIdx.y;
    const float* s;
    __half* d;
    int n4;
    if (seg == 0) {
        s = x; d = xh; n4 = Mrows * EMB / 4;
    } else {
        const float* ws[4] = {wq, wk, wv, wo};
        s = ws[seg - 1];
        d = wh + (size_t)(seg - 1) * EMB * EMB;
        n4 = EMB * EMB / 4;
    }
    int i = blockIdx.x * blockDim.x + threadIdx.x;
    if (i >= n4) return;
    float4 v = ((const float4*)s)[i];
    __half2* dp = (__half2*)(d + 4 * (size_t)i);
    dp[0] = __floats2half2_rn(v.x, v.y);
    dp[1] = __floats2half2_rn(v.z, v.w);
}

// -------- GEMM: C[m][n] = sum_k A[m][k] * W[n][k], fp16 in / fp32 acc --------
// BM=128, BN=128, BK=64. 128 threads (4 warps), warp tile 64x64 -> halves
// smem fragment traffic per MAC vs 32x64. 3-stage cp.async ring, ONE sync/iter.
// qkv_mode=1: half out + fused RoPE on z<2 (z==0 also applies QSCALE).
// qkv_mode=0: fp32 out to Cf.

constexpr int GST = 32768;  // stage bytes (A 16KB + B 16KB)
constexpr int GEMM_SMEM = 3 * GST;  // 98304

__global__ __launch_bounds__(128, 2) void gemm_h(
    const __half* __restrict__ A,
    const __half* __restrict__ W0, const __half* __restrict__ W1, const __half* __restrict__ W2,
    __half* __restrict__ H0, __half* __restrict__ H1, __half* __restrict__ H2,
    float* __restrict__ Cf,
    const float* __restrict__ cosv, const float* __restrict__ sinv,
    int qkv_mode, int K, int N) {
    const int z = blockIdx.z;
    const __half* W = (z == 0) ? W0 : (z == 1 ? W1 : W2);
    __half* Hc = (z == 0) ? H0 : (z == 1 ? H1 : H2);

    extern __shared__ char sm[];
    const uint32_t base = (uint32_t)__cvta_generic_to_shared(sm);

    const int tid = threadIdx.x, lane = tid & 31, wid = tid >> 5;
    const int g = lane >> 2, m4 = lane & 3;
    const int wm = wid >> 1, wn = wid & 1;   // 2x2 warps, 64x64 tile each
    const int lr = lane & 7, hb = (lane >> 3) & 1, kh = lane >> 4;
    const int bm = blockIdx.y * 128, bn = blockIdx.x * 128;
    const __half* Ag = A + (size_t)bm * K;
    const __half* Wg = W + (size_t)bn * K;

    float acc[4][8][4];
#pragma unroll
    for (int mi = 0; mi < 4; mi++)
#pragma unroll
        for (int ni = 0; ni < 8; ni++)
#pragma unroll
            for (int q = 0; q < 4; q++) acc[mi][ni][q] = 0.f;

    auto load_stage = [&](int st, int kt) {
        uint32_t ab = base + (uint32_t)st * GST;
        uint32_t bb = ab + 16384;
#pragma unroll
        for (int p = 0; p < 8; p++) {
            int id = tid + 128 * p;
            int r = id >> 3, c = id & 7;
            uint32_t off = (uint32_t)r * 128 + (uint32_t)((c ^ (r & 7)) << 4);
            cpasync16(ab + off, Ag + (size_t)r * K + kt + c * 8);
            cpasync16(bb + off, Wg + (size_t)r * K + kt + c * 8);
        }
        asm volatile("cp.async.commit_group;");
    };

    const int NIT = K / 64;  // 32
    load_stage(0, 0);
    load_stage(1, 64);

    for (int it = 0; it < NIT; ++it) {
        if (it < NIT - 1) asm volatile("cp.async.wait_group 1;");
        else              asm volatile("cp.async.wait_group 0;");
        __syncthreads();
        // sync proves all warps finished compute(it-1); stage (it+2)%3 == (it-1)%3 is free
        if (it + 2 < NIT) load_stage((it + 2) % 3, (it + 2) * 64);

        uint32_t ab = base + (uint32_t)(it % 3) * GST;
        uint32_t bb = ab + 16384;

#pragma unroll
        for (int kk = 0; kk < 4; kk++) {
            uint32_t a[4][4], b[4][4];
#pragma unroll
            for (int mi = 0; mi < 4; mi++) {
                int r = wm * 64 + mi * 16 + lr + hb * 8;
                int ch = kk * 2 + kh;
                ldsm4(a[mi][0], a[mi][1], a[mi][2], a[mi][3],
                      ab + (uint32_t)r * 128 + (uint32_t)((ch ^ (r & 7)) << 4));
            }
#pragma unroll
            for (int ngi = 0; ngi < 4; ngi++) {
                int r = wn * 64 + ngi * 16 + lr + kh * 8;
                int ch = kk * 2 + hb;
                ldsm4(b[ngi][0], b[ngi][1], b[ngi][2], b[ngi][3],
                      bb + (uint32_t)r * 128 + (uint32_t)((ch ^ (r & 7)) << 4));
            }
#pragma unroll
            for (int mi = 0; mi < 4; mi++)
#pragma unroll
                for (int ngi = 0; ngi < 4; ngi++) {
                    mma_h(acc[mi][2 * ngi], a[mi], b[ngi][0], b[ngi][1]);
                    mma_h(acc[mi][2 * ngi + 1], a[mi], b[ngi][2], b[ngi][3]);
                }
        }
    }

    // epilogue (fused RoPE for Q/K in qkv_mode)
#pragma unroll
    for (int mi = 0; mi < 4; mi++) {
        int r0 = bm + wm * 64 + mi * 16 + g;
#pragma unroll
        for (int ni = 0; ni < 8; ni++) {
            int col = bn + wn * 64 + ni * 8 + 2 * m4;
            float v0 = acc[mi][ni][0], v1 = acc[mi][ni][1];
            float v2 = acc[mi][ni][2], v3 = acc[mi][ni][3];
            if (qkv_mode) {
                if (z < 2) {  // RoPE for Q (z=0, with scale) and K (z=1)
                    float scl = (z == 0) ? QSCALE : 1.0f;
                    int d2 = (col & (HD - 1)) >> 1;
                    {
                        int t = r0 & (Tv - 1);
                        float c = cosv[t * 64 + d2], s = sinv[t * 64 + d2];
                        float xx = v0, yy = v1;
                        v0 = (xx * c - yy * s) * scl;
                        v1 = (xx * s + yy * c) * scl;
                    }
                    {
                        int t = (r0 + 8) & (Tv - 1);
                        float c = cosv[t * 64 + d2], s = sinv[t * 64 + d2];
                        float xx = v2, yy = v3;
                        v2 = (xx * c - yy * s) * scl;
                        v3 = (xx * s + yy * c) * scl;
                    }
                }
                *(__half2*)(Hc + (size_t)r0 * N + col) = __floats2half2_rn(v0, v1);
                *(__half2*)(Hc + (size_t)(r0 + 8) * N + col) = __floats2half2_rn(v2, v3);
            } else {
                *(float2*)(Cf + (size_t)r0 * N + col) = make_float2(v0, v1);
                *(float2*)(Cf + (size_t)(r0 + 8) * N + col) = make_float2(v2, v3);
            }
        }
    }
}

// -------- Flash attention (non-causal), fp16 mma.sync --------
// Br=128 (8 warps x 16 rows), Bc=64, HD=128.
// 3-stage KV ring (32KB/stage), ONE sync per iteration.
// P converted C-frag -> A-frag in registers (no smem roundtrip).

constexpr int ATT_SMEM = 3 * 32768;  // 98304

__global__ __launch_bounds__(256, 1) void attn_h(
    const __half* __restrict__ Q, const __half* __restrict__ Kg,
    const __half* __restrict__ Vg, __half* __restrict__ O) {
    extern __shared__ char sm[];
    const uint32_t base = (uint32_t)__cvta_generic_to_shared(sm);

    const int tid = threadIdx.x, lane = tid & 31, wid = tid >> 5;
    const int g = lane >> 2, m4 = lane & 3;
    const int lr = lane & 7, hb = (lane >> 3) & 1, kh = lane >> 4;
    const int qb = blockIdx.x;
    const int b = blockIdx.y >> 4, h = blockIdx.y & 15;

    const __half* Qg = Q + ((size_t)(b * Tv) + (size_t)qb * 128) * EMB + h * HD;
    const __half* Kb = Kg + (size_t)(b * Tv) * EMB + h * HD;
    const __half* Vb = Vg + (size_t)(b * Tv) * EMB + h * HD;

    // stage Q tile into stage-0 region (rows of 128 halves, XOR swizzle)
#pragma unroll
    for (int p = 0; p < 8; p++) {
        int id = tid + 256 * p;
        int r = id >> 4, c = id & 15;
        cpasync16(base + (uint32_t)r * 256 + (uint32_t)((c ^ (r & 7)) << 4),
                  Qg + (size_t)r * EMB + c * 8);
    }
    asm volatile("cp.async.commit_group;");
    asm volatile("cp.async.wait_group 0;");
    __syncthreads();

    // Q fragments in registers: 8 k-steps x 4 regs
    uint32_t qf[8][4];
#pragma unroll
    for (int kk = 0; kk < 8; kk++) {
        int r = wid * 16 + lr + hb * 8;
        int ch = kk * 2 + kh;
        ldsm4(qf[kk][0], qf[kk][1], qf[kk][2], qf[kk][3],
              base + (uint32_t)r * 256 + (uint32_t)((ch ^ (r & 7)) << 4));
    }
    __syncthreads();  // all warps done reading Q before KV overwrites stage 0

    float mr0 = -1e30f, mr1 = -1e30f, l0 = 0.f, l1 = 0.f;
    float o[16][4];
#pragma unroll
    for (int nd = 0; nd < 16; nd++)
#pragma unroll
        for (int q = 0; q < 4; q++) o[nd][q] = 0.f;

    auto load_kv = [&](int j, int st) {
        uint32_t kb = base + (uint32_t)st * 32768;
        uint32_t vb = kb + 16384;
        const __half* kg = Kb + (size_t)j * 64 * EMB;
        const __half* vg = Vb + (size_t)j * 64 * EMB;
#pragma unroll
        for (int p = 0; p < 4; p++) {
            int id = tid + 256 * p;
            int r = id >> 4, c = id & 15;
            uint32_t off = (uint32_t)r * 256 + (uint32_t)((c ^ (r & 7)) << 4);
            cpasync16(kb + off, kg + (size_t)r * EMB + c * 8);
            cpasync16(vb + off, vg + (size_t)r * EMB + c * 8);
        }
        asm volatile("cp.async.commit_group;");
    };

    load_kv(0, 0);
    load_kv(1, 1);

    for (int j = 0; j < 32; j++) {
        if (j < 31) asm volatile("cp.async.wait_group 1;");
        else        asm volatile("cp.async.wait_group 0;");
        __syncthreads();
        // stage (j+2)%3 == (j-1)%3, finished by all warps at this sync
        if (j + 2 < 32) load_kv(j + 2, (j + 2) % 3);

        uint32_t kb = base + (uint32_t)(j % 3) * 32768;
        uint32_t vb = kb + 16384;

        // S = Q K^T (scale pre-folded into Q)
        float sa[8][4];
#pragma unroll
        for (int ni = 0; ni < 8; ni++)
#pragma unroll
            for (int q = 0; q < 4; q++) sa[ni][q] = 0.f;

#pragma unroll
        for (int kk = 0; kk < 8; kk++) {
            uint32_t bf[4][4];
#pragma unroll
            for (int ngi = 0; ngi < 4; ngi++) {
                int r = ngi * 16 + lr + kh * 8;
                int ch = kk * 2 + hb;
                ldsm4(bf[ngi][0], bf[ngi][1], bf[ngi][2], bf[ngi][3],
                      kb + (uint32_t)r * 256 + (uint32_t)((ch ^ (r & 7)) << 4));
            }
#pragma unroll
            for (int ngi = 0; ngi < 4; ngi++) {
                mma_h(sa[2 * ngi], qf[kk], bf[ngi][0], bf[ngi][1]);
                mma_h(sa[2 * ngi + 1], qf[kk], bf[ngi][2], bf[ngi][3]);
            }
        }

        // online softmax (rows g and g+8), base-2 domain
        float c0 = -1e30f, c1 = -1e30f;
#pragma unroll
        for (int ni = 0; ni < 8; ni++) {
            c0 = fmaxf(c0, fmaxf(sa[ni][0], sa[ni][1]));
            c1 = fmaxf(c1, fmaxf(sa[ni][2], sa[ni][3]));
        }
        c0 = fmaxf(c0, __shfl_xor_sync(FULLMASK, c0, 1));
        c0 = fmaxf(c0, __shfl_xor_sync(FULLMASK, c0, 2));
        c1 = fmaxf(c1, __shfl_xor_sync(FULLMASK, c1, 1));
        c1 = fmaxf(c1, __shfl_xor_sync(FULLMASK, c1, 2));

        float mn0 = fmaxf(mr0, c0), mn1 = fmaxf(mr1, c1);
        float al0 = exp2f(mr0 - mn0), al1 = exp2f(mr1 - mn1);
        mr0 = mn0; mr1 = mn1;

        float rs0 = 0.f, rs1 = 0.f;
#pragma unroll
        for (int ni = 0; ni < 8; ni++) {
            sa[ni][0] = exp2f(sa[ni][0] - mn0);
            sa[ni][1] = exp2f(sa[ni][1] - mn0);
            sa[ni][2] = exp2f(sa[ni][2] - mn1);
            sa[ni][3] = exp2f(sa[ni][3] - mn1);
            rs0 += sa[ni][0] + sa[ni][1];
            rs1 += sa[ni][2] + sa[ni][3];
        }
        rs0 += __shfl_xor_sync(FULLMASK, rs0, 1);
        rs0 += __shfl_xor_sync(FULLMASK, rs0, 2);
        rs1 += __shfl_xor_sync(FULLMASK, rs1, 1);
        rs1 += __shfl_xor_sync(FULLMASK, rs1, 2);
        l0 = l0 * al0 + rs0;
        l1 = l1 * al1 + rs1;

#pragma unroll
        for (int nd = 0; nd < 16; nd++) {
            o[nd][0] *= al0; o[nd][1] *= al0;
            o[nd][2] *= al1; o[nd][3] *= al1;
        }

        // O += P @ V ; P C-frag -> A-frag packed in registers
#pragma unroll
        for (int kk2 = 0; kk2 < 4; kk2++) {
            uint32_t pa[4];
            pa[0] = h2u(sa[2 * kk2][0], sa[2 * kk2][1]);
            pa[1] = h2u(sa[2 * kk2][2], sa[2 * kk2][3]);
            pa[2] = h2u(sa[2 * kk2 + 1][0], sa[2 * kk2 + 1][1]);
            pa[3] = h2u(sa[2 * kk2 + 1][2], sa[2 * kk2 + 1][3]);
            int r = kk2 * 16 + lr + hb * 8;
#pragma unroll
            for (int ndg = 0; ndg < 8; ndg++) {
                int ch = ndg * 2 + kh;
                uint32_t v0, v1, v2, v3;
                ldsm4t(v0, v1, v2, v3,
                       vb + (uint32_t)r * 256 + (uint32_t)((ch ^ (r & 7)) << 4));
                mma_h(o[2 * ndg], pa, v0, v1);
                mma_h(o[2 * ndg + 1], pa, v2, v3);
            }
        }
    }

    float inv0 = 1.f / l0, inv1 = 1.f / l1;
    size_t row0 = (size_t)(b * Tv) + (size_t)qb * 128 + wid * 16 + g;
    __half* Op = O + row0 * EMB + h * HD;
#pragma unroll
    for (int nd = 0; nd < 16; nd++) {
        int col = nd * 8 + 2 * m4;
        *(__half2*)(Op + col) = __floats2half2_rn(o[nd][0] * inv0, o[nd][1] * inv0);
        *(__half2*)(Op + (size_t)8 * EMB + col) = __floats2half2_rn(o[nd][2] * inv1, o[nd][3] * inv1);
    }
}

// -------- launch --------
extern "C" void kernel_launch(void* const* d_in, const int* in_sizes, int n_in,
                              void* d_out, int out_size) {
    const float* x  = (const float*)d_in[0];
    const float* wq = (const float*)d_in[1];
    const float* wk = (const float*)d_in[2];
    const float* wv = (const float*)d_in[3];
    const float* wo = (const float*)d_in[4];
    const float* fc = (const float*)d_in[7];
    const float* fs = (const float*)d_in[8];
    float* out = (float*)d_out;

    __half *xh, *wh, *qh, *kh, *vh, *oh;
    cudaGetSymbolAddress((void**)&xh, g_xh);
    cudaGetSymbolAddress((void**)&wh, g_wh);
    cudaGetSymbolAddress((void**)&qh, g_qh);
    cudaGetSymbolAddress((void**)&kh, g_kh);
    cudaGetSymbolAddress((void**)&vh, g_vh);
    cudaGetSymbolAddress((void**)&oh, g_oh);
    __half* wqh = wh;
    __half* wkh = wh + (size_t)EMB * EMB;
    __half* wvh = wh + 2 * (size_t)EMB * EMB;
    __half* woh = wh + 3 * (size_t)EMB * EMB;

    cudaFuncSetAttribute(gemm_h, cudaFuncAttributeMaxDynamicSharedMemorySize, GEMM_SMEM);
    cudaFuncSetAttribute(attn_h, cudaFuncAttributeMaxDynamicSharedMemorySize, ATT_SMEM);

    // fp32 -> fp16 converts (one launch, 5 segments)
    f2h_all<<<dim3(Mrows * EMB / 4 / 256, 5), 256>>>(x, wq, wk, wv, wo, xh, wh);

    // fused QKV projection + RoPE (+softmax scale on Q) in epilogue
    gemm_h<<<dim3(EMB / 128, Mrows / 128, 3), 128, GEMM_SMEM>>>(
        xh, wqh, wkh, wvh, qh, kh, vh, nullptr, fc, fs, 1, EMB, EMB);

    // flash attention
    attn_h<<<dim3(Tv / 128, Bv * Hh), 256, ATT_SMEM>>>(qh, kh, vh, oh);

    // output projection (fp32 out)
    gemm_h<<<dim3(EMB / 128, Mrows / 128, 1), 128, GEMM_SMEM>>>(
        oh, woh, woh, woh, nullptr, nullptr, nullptr, out, nullptr, nullptr, 0, EMB, EMB);
}